// round 17
// baseline (speedup 1.0000x reference)
#include <cuda_runtime.h>
#include <cuda_bf16.h>
#include <mma.h>
#include <cstdint>

#define BB 16
#define NN 2048
#define NCTX 2047
#define EMB 64
#define DIN 160
#define NLAYERS 3
#define CHN 128
#define ACH 16
#define CCW 64

typedef unsigned long long ull;
using namespace nvcuda;

#define PACK2(d, x)      asm("mov.b64 %0, {%1, %1};" : "=l"(d) : "f"(x))
#define UNPACK2(lo, hi, v) asm("mov.b64 {%0, %1}, %2;" : "=f"(lo), "=f"(hi) : "l"(v))
#define FMA2(d, a, b, c) asm("fma.rn.f32x2 %0, %1, %2, %3;" : "=l"(d) : "l"(a), "l"(b), "l"(c))

// Scratch (allocation-free rule: device globals)
__device__ float g_Rpart[BB * ACH * 96 * 32];   // per-(batch,chunk) partial R
__device__ float g_R[BB * 96 * 32];             // reduced R per batch
__device__ float g_P[BB * 64 * 32];             // P[c][j] per batch

// ---------------- Kernel A: Rpart = x[0:96,chunk] @ x[0:32,chunk]^T (pipelined) ------
extern "C" __global__ void __launch_bounds__(256) kA(const float* __restrict__ x) {
    extern __shared__ float sx[]; // [CHN][98]
    const int b = blockIdx.y, ch = blockIdx.x, tid = threadIdx.x;
    const int n0 = ch * CHN;
    const int count = min(CHN, NCTX - n0);
    const float* xb = x + (size_t)b * DIN * NN;
    for (int i = tid; i < 96 * CHN; i += 256) {
        int r = i >> 7, n = i & 127;
        sx[n * 98 + r] = (n < count) ? xb[r * NN + n0 + n] : 0.f;
    }
    __syncthreads();
    const int tc = tid & 15, tr = tid >> 4;
    const int r0 = tr * 6, j0 = tc * 2;
    ull acc[3][2];
#pragma unroll
    for (int p = 0; p < 3; p++) { acc[p][0] = 0ull; acc[p][1] = 0ull; }
    const float* row = sx + r0;
    const float* qrow = sx + j0;
    ull a0 = *(const ull*)(row);
    ull a1 = *(const ull*)(row + 2);
    ull a2 = *(const ull*)(row + 4);
    float2 q = *(const float2*)(qrow);
#pragma unroll 4
    for (int n = 0; n < CHN - 1; n++) {
        const float* rn = row + (n + 1) * 98;
        const float* qn = qrow + (n + 1) * 98;
        ull b0 = *(const ull*)(rn);
        ull b1 = *(const ull*)(rn + 2);
        ull b2 = *(const ull*)(rn + 4);
        float2 q2 = *(const float2*)(qn);
        ull q0, q1;
        PACK2(q0, q.x); PACK2(q1, q.y);
        FMA2(acc[0][0], a0, q0, acc[0][0]); FMA2(acc[0][1], a0, q1, acc[0][1]);
        FMA2(acc[1][0], a1, q0, acc[1][0]); FMA2(acc[1][1], a1, q1, acc[1][1]);
        FMA2(acc[2][0], a2, q0, acc[2][0]); FMA2(acc[2][1], a2, q1, acc[2][1]);
        a0 = b0; a1 = b1; a2 = b2; q = q2;
    }
    {
        ull q0, q1;
        PACK2(q0, q.x); PACK2(q1, q.y);
        FMA2(acc[0][0], a0, q0, acc[0][0]); FMA2(acc[0][1], a0, q1, acc[0][1]);
        FMA2(acc[1][0], a1, q0, acc[1][0]); FMA2(acc[1][1], a1, q1, acc[1][1]);
        FMA2(acc[2][0], a2, q0, acc[2][0]); FMA2(acc[2][1], a2, q1, acc[2][1]);
    }
    float* outp = g_Rpart + (size_t)(b * ACH + ch) * 3072;
#pragma unroll
    for (int p = 0; p < 3; p++) {
        float l0, h0, l1, h1;
        UNPACK2(l0, h0, acc[p][0]);
        UNPACK2(l1, h1, acc[p][1]);
        *(float2*)(outp + (r0 + 2 * p) * 32 + j0)     = make_float2(l0, l1);
        *(float2*)(outp + (r0 + 2 * p + 1) * 32 + j0) = make_float2(h0, h1);
    }
}

// ---------------- Kernel R: reduce ACH partials -> g_R ----------------
extern "C" __global__ void kR() {
    const int b = blockIdx.x;
    const int e = blockIdx.y * 256 + threadIdx.x;
    const float* p = g_Rpart + (size_t)b * ACH * 3072 + e;
    float s = 0.f;
#pragma unroll
    for (int c = 0; c < ACH; c++) s += p[c * 3072];
    g_R[b * 3072 + e] = s;
}

// ---------------- Kernel B: per-batch tiny algebra -> P ----------------
extern "C" __global__ void kB(const float* __restrict__ alpha,
                              const float* __restrict__ kp_,
                              const float* __restrict__ E,
                              const float* __restrict__ M) {
    extern __shared__ float smb[];
    float* sE   = smb;
    float* sM   = sE + 4096;
    float* sR   = sM + 4096;
    float* sW   = sR + 3072;
    float* sS   = sW + 2048;
    float* sT   = sS + 2048;
    float* sSum = sT + 2048;
    const int b = blockIdx.x, tid = threadIdx.x;
    for (int i = tid; i < 4096; i += 512) { sE[i] = E[i]; sM[i] = M[i]; }
    for (int i = tid; i < 3072; i += 512) sR[i] = g_R[b * 3072 + i];
    for (int i = tid; i < 2048; i += 512) sSum[i] = 0.f;
    __syncthreads();

    const int i0 = tid >> 3;
    const int j0 = (tid & 7) * 4;
    const float* sC = sR + 32 * 32;
    {
        float a0 = 0, a1 = 0, a2 = 0, a3 = 0;
#pragma unroll
        for (int k = 0; k < 64; k++) {
            float e = sE[i0 * 64 + k];
            float4 cv = *(const float4*)(sC + k * 32 + j0);
            a0 += e * cv.x; a1 += e * cv.y; a2 += e * cv.z; a3 += e * cv.w;
        }
        *(float4*)(sW + i0 * 32 + j0) = make_float4(a0, a1, a2, a3);
    }
    __syncthreads();

    const float kp = kp_[0];
    for (int l = 0; l < NLAYERS; l++) {
        float sc = kp * alpha[l * EMB + i0] * (1.0f / (float)NCTX);
        {
            float4 wv = *(const float4*)(sW + i0 * 32 + j0);
            float4 sv = make_float4(sc * wv.x, sc * wv.y, sc * wv.z, sc * wv.w);
            *(float4*)(sS + i0 * 32 + j0) = sv;
            float4 su = *(const float4*)(sSum + i0 * 32 + j0);
            su.x += sv.x; su.y += sv.y; su.z += sv.z; su.w += sv.w;
            *(float4*)(sSum + i0 * 32 + j0) = su;
        }
        __syncthreads();
        if (l < NLAYERS - 1) {
            float a0 = 0, a1 = 0, a2 = 0, a3 = 0;
#pragma unroll
            for (int k = 0; k < 64; k++) {
                float m = sM[i0 * 64 + k];
                float4 sv = *(const float4*)(sS + k * 32 + j0);
                a0 += m * sv.x; a1 += m * sv.y; a2 += m * sv.z; a3 += m * sv.w;
            }
            *(float4*)(sT + i0 * 32 + j0) = make_float4(a0, a1, a2, a3);
            __syncthreads();
            a0 = 0; a1 = 0; a2 = 0; a3 = 0;
#pragma unroll
            for (int p = 0; p < 32; p++) {
                float t = sT[i0 * 32 + p];
                float4 gv = *(const float4*)(sR + p * 32 + j0);
                a0 += t * gv.x; a1 += t * gv.y; a2 += t * gv.z; a3 += t * gv.w;
            }
            float4 wv = *(const float4*)(sW + i0 * 32 + j0);
            wv.x += a0; wv.y += a1; wv.z += a2; wv.w += a3;
            *(float4*)(sW + i0 * 32 + j0) = wv;
            __syncthreads();
        }
    }
    {
        float a0 = 0, a1 = 0, a2 = 0, a3 = 0;
#pragma unroll
        for (int d = 0; d < 64; d++) {
            float e = sE[d * 64 + i0];
            float4 sv = *(const float4*)(sSum + d * 32 + j0);
            a0 += e * sv.x; a1 += e * sv.y; a2 += e * sv.z; a3 += e * sv.w;
        }
        *(float4*)(g_P + (size_t)(b * 64 + i0) * 32 + j0) = make_float4(a0, a1, a2, a3);
    }
}

// ---------------- Kernel C (wmma): logits = V^T @ U via bf16 hi/lo HMMA ----------------
// Per CTA: D[m=64 cols][n=64 classes], K=96. A = V^T [m][k] bf16 hi/lo (k-major,
// stride 104), B = U [k][n] accessed col-major from sB[n][k]. 8 warps, each
// 1 m16-tile x 2 n16-tiles, 6 k-steps x 3 combos (AhBh + AhBl + AlBh).
#define LDA 104
#define LDD 68
extern "C" __global__ void __launch_bounds__(256) kC(const float* __restrict__ x,
                                                     const float* __restrict__ E,
                                                     float* __restrict__ out) {
    extern __shared__ char smw[];
    __nv_bfloat16* sAh = (__nv_bfloat16*)smw;              // 64 x 104
    __nv_bfloat16* sAl = sAh + 64 * LDA;                   // 64 x 104
    __nv_bfloat16* sBh = sAl + 64 * LDA;                   // 64 x 104
    __nv_bfloat16* sBl = sBh + 64 * LDA;                   // 64 x 104
    float* sD = (float*)smw;                               // 64 x 68 (aliases sA after mma)

    const int b = blockIdx.y, chn = blockIdx.x, tid = threadIdx.x;
    const int wid = tid >> 5;
    const int n0 = chn * CCW;
    const float* xb = x + (size_t)b * DIN * NN;

    // A = V^T: A[m][k]; k<64 -> f0 row (96+k), else xq row (k-64); col n0+m.
    for (int i = tid; i < 96 * 64; i += 256) {
        int k = i >> 6, m = i & 63;
        int row = (k < 64) ? (96 + k) : (k - 64);
        float v = xb[(size_t)row * NN + n0 + m];
        __nv_bfloat16 h = __float2bfloat16(v);
        __nv_bfloat16 l = __float2bfloat16(v - __bfloat162float(h));
        sAh[m * LDA + k] = h;
        sAl[m * LDA + k] = l;
    }
    // B stored as sB[n=class][k]: U[k][c]; k<64 -> E[k*64+c], else P[c][k-64].
    for (int i = tid; i < 96 * 64; i += 256) {
        int k = i >> 6, c = i & 63;
        float v = (k < 64) ? E[k * 64 + c] : g_P[(size_t)(b * 64 + c) * 32 + (k - 64)];
        __nv_bfloat16 h = __float2bfloat16(v);
        __nv_bfloat16 l = __float2bfloat16(v - __bfloat162float(h));
        sBh[c * LDA + k] = h;
        sBl[c * LDA + k] = l;
    }
    // zero-pad k = 96..103 (fragments only read k<96; pad keeps loads in-bounds)
    for (int i = tid; i < 64 * 8; i += 256) {
        int m = i >> 3, k = 96 + (i & 7);
        sAh[m * LDA + k] = __float2bfloat16(0.f);
        sAl[m * LDA + k] = __float2bfloat16(0.f);
        sBh[m * LDA + k] = __float2bfloat16(0.f);
        sBl[m * LDA + k] = __float2bfloat16(0.f);
    }
    __syncthreads();

    // warp w: m-tile = w & 3 (m0 = 16*(w&3)); n-half = w >> 2 (n 32-wide)
    const int m0 = (wid & 3) * 16;
    const int nh = (wid >> 2) * 32;
    wmma::fragment<wmma::accumulator, 16, 16, 16, float> acc[2];
    wmma::fill_fragment(acc[0], 0.f);
    wmma::fill_fragment(acc[1], 0.f);
#pragma unroll
    for (int ks = 0; ks < 6; ks++) {
        const int k0 = ks * 16;
        wmma::fragment<wmma::matrix_a, 16, 16, 16, __nv_bfloat16, wmma::row_major> ah, al;
        wmma::load_matrix_sync(ah, sAh + m0 * LDA + k0, LDA);
        wmma::load_matrix_sync(al, sAl + m0 * LDA + k0, LDA);
#pragma unroll
        for (int j = 0; j < 2; j++) {
            wmma::fragment<wmma::matrix_b, 16, 16, 16, __nv_bfloat16, wmma::col_major> bh, bl;
            wmma::load_matrix_sync(bh, sBh + (nh + 16 * j) * LDA + k0, LDA);
            wmma::load_matrix_sync(bl, sBl + (nh + 16 * j) * LDA + k0, LDA);
            wmma::mma_sync(acc[j], ah, bh, acc[j]);
            wmma::mma_sync(acc[j], ah, bl, acc[j]);
            wmma::mma_sync(acc[j], al, bh, acc[j]);
        }
    }
    __syncthreads();   // all sA/sB reads done before aliasing with sD
    wmma::store_matrix_sync(sD + m0 * LDD + nh,      acc[0], LDD, wmma::mem_row_major);
    wmma::store_matrix_sync(sD + m0 * LDD + nh + 16, acc[1], LDD, wmma::mem_row_major);
    __syncthreads();

    // Epilogue: 4 threads per column m = tid>>2; each owns 16 classes.
    const int m = tid >> 2;                 // 0..63
    const int chh = (tid & 3) * 16;         // 0,16,32,48
    float v[16];
#pragma unroll
    for (int c = 0; c < 16; c += 4) {
        float4 r = *(const float4*)(sD + m * LDD + chh + c);
        v[c] = r.x; v[c + 1] = r.y; v[c + 2] = r.z; v[c + 3] = r.w;
    }
    float* gl = out + ((size_t)(b * NN + n0 + m)) * 64 + chh;
    float* gp = gl + (size_t)BB * NN * 64;
#pragma unroll
    for (int c = 0; c < 16; c += 4)
        *(float4*)(gl + c) = make_float4(v[c], v[c + 1], v[c + 2], v[c + 3]);
    float mx = v[0];
#pragma unroll
    for (int c = 1; c < 16; c++) mx = fmaxf(mx, v[c]);
    mx = fmaxf(mx, __shfl_xor_sync(0xffffffffu, mx, 1));
    mx = fmaxf(mx, __shfl_xor_sync(0xffffffffu, mx, 2));
    float s = 0.f;
#pragma unroll
    for (int c = 0; c < 16; c++) { v[c] = __expf(v[c] - mx); s += v[c]; }
    s += __shfl_xor_sync(0xffffffffu, s, 1);
    s += __shfl_xor_sync(0xffffffffu, s, 2);
    float inv = __frcp_rn(s);
#pragma unroll
    for (int c = 0; c < 16; c += 4)
        *(float4*)(gp + c) = make_float4(v[c] * inv, v[c + 1] * inv, v[c + 2] * inv, v[c + 3] * inv);
}

extern "C" void kernel_launch(void* const* d_in, const int* in_sizes, int n_in,
                              void* d_out, int out_size) {
    const float* x     = (const float*)d_in[0];
    const float* alpha = (const float*)d_in[1];
    const float* kp    = (const float*)d_in[2];
    const float* E     = (const float*)d_in[3];
    const float* M     = (const float*)d_in[4];
    float* out = (float*)d_out;

    const int smemA = CHN * 98 * 4;                 // 50,176 B
    const int smemB = (4096*2 + 3072 + 2048*4) * 4; // 77,824 B
    const int smemC = 4 * 64 * LDA * 2;             // 53,248 B
    cudaFuncSetAttribute(kA, cudaFuncAttributeMaxDynamicSharedMemorySize, smemA);
    cudaFuncSetAttribute(kB, cudaFuncAttributeMaxDynamicSharedMemorySize, smemB);
    cudaFuncSetAttribute(kC, cudaFuncAttributeMaxDynamicSharedMemorySize, smemC);

    kA<<<dim3(ACH, BB), 256, smemA>>>(x);
    kR<<<dim3(BB, 12), 256>>>();
    kB<<<BB, 512, smemB>>>(alpha, kp, E, M);
    kC<<<dim3(NN / CCW, BB), 256, smemC>>>(x, E, out);
}